// round 4
// baseline (speedup 1.0000x reference)
#include <cuda_runtime.h>
#include <cstdint>

// Problem constants (fixed by setup_inputs)
#define B_   64
#define NO_  1024
#define NI_  1024
#define NBT  8                   // batches per block == pipeline slots
#define ROW_BYTES (NI_ * 4)      // 4096 B per (b,j) row

// RHO_R = exp(-DT/TAU_R) = exp(-0.05)
__device__ __constant__ float kRhoR = 0.95122942450071400910f;

__device__ __forceinline__ uint32_t smem_u32(const void* p) {
    uint32_t a;
    asm("{ .reg .u64 t; cvta.to.shared.u64 t, %1; cvt.u32.u64 %0, t; }"
        : "=r"(a) : "l"(p));
    return a;
}

__device__ __forceinline__ void mbar_wait_parity0(uint32_t bar) {
    asm volatile(
        "{\n\t"
        ".reg .pred P;\n\t"
        "WL_%=:\n\t"
        "mbarrier.try_wait.parity.acquire.cta.shared::cta.b64 P, [%0], 0, 0x989680;\n\t"
        "@P bra.uni WD_%=;\n\t"
        "bra.uni WL_%=;\n\t"
        "WD_%=:\n\t"
        "}" :: "r"(bar) : "memory");
}

// Block = (j, tile of NBT batches). 256 threads x float4 = 1024 = NI.
// All NBT hIsyn rows fetched via cp.async.bulk into smem (zero register
// cost, 32KB in flight per CTA). Compute in-place in smem, then TMA bulk
// store each 4KB row back out. rho/w register-cached across batches.
__global__ void __launch_bounds__(256)
hetsyn_cell_kernel(const float* __restrict__ x,      // (B, NI)
                   const float* __restrict__ w,      // (NO, NI)
                   const float* __restrict__ rho,    // (NO, NI)
                   const float* __restrict__ hz,     // (B, NO)
                   const float* __restrict__ hIsyn,  // (B, NO, NI)
                   const float* __restrict__ hIr,    // (B, NO)
                   float* __restrict__ z_out,        // (B, NO)
                   float* __restrict__ Isyn_out,     // (B, NO, NI)
                   float* __restrict__ Ir_out)       // (B, NO)
{
    __shared__ __align__(128) float   buf[NBT][NI_];   // 32 KB
    __shared__ __align__(8)   uint64_t mbar[NBT];
    __shared__ float wsum[8][NBT];

    const int j  = blockIdx.x;
    const int b0 = blockIdx.y * NBT;
    const int t  = threadIdx.x;

    const size_t wrow = (size_t)j * NI_;
    const float4 rv = __ldg(reinterpret_cast<const float4*>(rho + wrow) + t);
    const float4 wv = __ldg(reinterpret_cast<const float4*>(w   + wrow) + t);

    const uint32_t sbase = smem_u32(buf);
    const uint32_t mb    = smem_u32(mbar);

    if (t == 0) {
        #pragma unroll
        for (int k = 0; k < NBT; ++k)
            asm volatile("mbarrier.init.shared.b64 [%0], 1;"
                         :: "r"(mb + 8u * k) : "memory");
    }
    __syncthreads();

    // ---- Prologue: issue ALL NBT bulk loads (deep async pipeline) ----
    if (t == 0) {
        #pragma unroll
        for (int k = 0; k < NBT; ++k) {
            const uint32_t bar = mb + 8u * k;
            asm volatile("mbarrier.arrive.expect_tx.shared.b64 _, [%0], %1;"
                         :: "r"(bar), "r"(ROW_BYTES) : "memory");
            const float* src = hIsyn + ((size_t)(b0 + k) * NO_ + j) * (size_t)NI_;
            asm volatile(
                "cp.async.bulk.shared::cluster.global.mbarrier::complete_tx::bytes "
                "[%0], [%1], %2, [%3];"
                :: "r"(sbase + (uint32_t)k * ROW_BYTES), "l"(src),
                   "r"(ROW_BYTES), "r"(bar) : "memory");
        }
    }

    // ---- Main loop: consume slot, compute in place, TMA-store it ----
    float psum[NBT];
    #pragma unroll
    for (int bb = 0; bb < NBT; ++bb) {
        mbar_wait_parity0(mb + 8u * bb);

        const float4 hv = *reinterpret_cast<const float4*>(&buf[bb][t * 4]);
        const float4 xv = __ldg(
            reinterpret_cast<const float4*>(x + (size_t)(b0 + bb) * NI_) + t);

        float4 Is;
        Is.x = fmaf(rv.x, hv.x, wv.x * xv.x);
        Is.y = fmaf(rv.y, hv.y, wv.y * xv.y);
        Is.z = fmaf(rv.z, hv.z, wv.z * xv.z);
        Is.w = fmaf(rv.w, hv.w, wv.w * xv.w);

        *reinterpret_cast<float4*>(&buf[bb][t * 4]) = Is;   // in-place
        psum[bb] = (Is.x + Is.y) + (Is.z + Is.w);

        __syncthreads();   // all STS for slot bb visible

        if (t == 0) {
            asm volatile("fence.proxy.async.shared::cta;" ::: "memory");
            float* dst = Isyn_out + ((size_t)(b0 + bb) * NO_ + j) * (size_t)NI_;
            asm volatile(
                "cp.async.bulk.global.shared::cta.bulk_group [%0], [%1], %2;"
                :: "l"(dst), "r"(sbase + (uint32_t)bb * ROW_BYTES),
                   "r"(ROW_BYTES) : "memory");
            asm volatile("cp.async.bulk.commit_group;" ::: "memory");
        }
    }

    // ---- Row-sum reduction (per batch), then scalar neuron update ----
    #pragma unroll
    for (int bb = 0; bb < NBT; ++bb) {
        #pragma unroll
        for (int off = 16; off > 0; off >>= 1)
            psum[bb] += __shfl_down_sync(0xFFFFFFFFu, psum[bb], off);
    }

    const int lane = t & 31;
    const int warp = t >> 5;
    if (lane == 0) {
        #pragma unroll
        for (int bb = 0; bb < NBT; ++bb) wsum[warp][bb] = psum[bb];
    }
    __syncthreads();

    if (t < NBT) {
        float v_in = 0.0f;
        #pragma unroll
        for (int k = 0; k < 8; ++k) v_in += wsum[k][t];

        const int b    = b0 + t;
        const int oidx = b * NO_ + j;

        const float Ir = fmaf(kRhoR, hIr[oidx], hz[oidx]);
        Ir_out[oidx] = Ir;
        // v = v_in - THR*Ir; z = (v - THR >= 0), THR = 1
        z_out[oidx]  = (v_in - Ir - 1.0f >= 0.0f) ? 1.0f : 0.0f;
    }

    // Drain bulk-store groups before exit (issued by t==0 only)
    if (t == 0)
        asm volatile("cp.async.bulk.wait_group 0;" ::: "memory");
}

extern "C" void kernel_launch(void* const* d_in, const int* in_sizes, int n_in,
                              void* d_out, int out_size)
{
    // Input order per setup_inputs: x, w, rho, hz, hIsyn, hIr
    const float* x     = (const float*)d_in[0];
    const float* w     = (const float*)d_in[1];
    const float* rho   = (const float*)d_in[2];
    const float* hz    = (const float*)d_in[3];
    const float* hIsyn = (const float*)d_in[4];
    const float* hIr   = (const float*)d_in[5];

    // Output tuple (z, Isyn, Ir) flattened + concatenated
    float* out    = (float*)d_out;
    float* z_out  = out;
    float* Isyn_o = out + (size_t)B_ * NO_;
    float* Ir_out = out + (size_t)B_ * NO_ + (size_t)B_ * NO_ * NI_;

    dim3 grid(NO_, B_ / NBT);   // (1024, 8) = 8192 blocks
    dim3 block(256);
    hetsyn_cell_kernel<<<grid, block>>>(x, w, rho, hz, hIsyn, hIr,
                                        z_out, Isyn_o, Ir_out);
}

// round 5
// speedup vs baseline: 1.0423x; 1.0423x over previous
#include <cuda_runtime.h>
#include <cstdint>

// Problem constants (fixed by setup_inputs)
#define B_   64
#define NO_  1024
#define NI_  1024
#define NBT  8                     // batches (pipeline slots) per block
#define ROW_BYTES (NI_ * 4)        // 4096 B per (b,j) row

// RHO_R = exp(-DT/TAU_R) = exp(-0.05)
__device__ __constant__ float kRhoR = 0.95122942450071400910f;

__device__ __forceinline__ uint32_t smem_u32(const void* p) {
    uint32_t a;
    asm("{ .reg .u64 t; cvta.to.shared.u64 t, %1; cvt.u32.u64 %0, t; }"
        : "=r"(a) : "l"(p));
    return a;
}

template<int PENDING>
__device__ __forceinline__ void cp_wait() {
    asm volatile("cp.async.wait_group %0;" :: "n"(PENDING) : "memory");
}

// Block = (j, tile of NBT batches). 256 threads x float4 = 1024 = NI.
// hIsyn streamed via per-thread cp.async.cg (16B each, zero register cost,
// 8 groups in flight). Each thread consumes ONLY the bytes it copied, and
// cp.async groups retire in order -> NO block barriers in the hot loop.
// rho/w register-cached; stores go straight from registers (STG.cs).
__global__ void __launch_bounds__(256)
hetsyn_cell_kernel(const float* __restrict__ x,      // (B, NI)
                   const float* __restrict__ w,      // (NO, NI)
                   const float* __restrict__ rho,    // (NO, NI)
                   const float* __restrict__ hz,     // (B, NO)
                   const float* __restrict__ hIsyn,  // (B, NO, NI)
                   const float* __restrict__ hIr,    // (B, NO)
                   float* __restrict__ z_out,        // (B, NO)
                   float* __restrict__ Isyn_out,     // (B, NO, NI)
                   float* __restrict__ Ir_out)       // (B, NO)
{
    __shared__ __align__(128) float buf[NBT][NI_];   // 32 KB
    __shared__ float wsum[8][NBT];

    const int j  = blockIdx.x;
    const int b0 = blockIdx.y * NBT;
    const int t  = threadIdx.x;

    const size_t wrow = (size_t)j * NI_;
    const float4 rv = __ldg(reinterpret_cast<const float4*>(rho + wrow) + t);
    const float4 wv = __ldg(reinterpret_cast<const float4*>(w   + wrow) + t);

    const uint32_t sbase = smem_u32(buf) + (uint32_t)t * 16u;

    // ---- Issue all NBT streaming loads as separate in-order groups ----
    {
        const float* src = hIsyn + ((size_t)b0 * NO_ + j) * (size_t)NI_ + (size_t)t * 4;
        #pragma unroll
        for (int k = 0; k < NBT; ++k) {
            asm volatile(
                "cp.async.cg.shared.global [%0], [%1], 16;\n\t"
                "cp.async.commit_group;"
                :: "r"(sbase + (uint32_t)k * ROW_BYTES), "l"(src) : "memory");
            src += (size_t)NO_ * NI_;
        }
    }

    // ---- Staged consumption: compute slot bb while later slots fly ----
    float psum[NBT];

    float4* qst = reinterpret_cast<float4*>(
        Isyn_out + ((size_t)b0 * NO_ + j) * (size_t)NI_) + t;

#define HSN_STEP(bb)                                                          \
    {                                                                         \
        cp_wait<NBT - 1 - (bb)>();                                            \
        const float4 hv = *reinterpret_cast<const float4*>(                   \
            &buf[(bb)][t * 4]);                                               \
        const float4 xv = __ldg(reinterpret_cast<const float4*>(              \
            x + (size_t)(b0 + (bb)) * NI_) + t);                              \
        float4 Is;                                                            \
        Is.x = fmaf(rv.x, hv.x, wv.x * xv.x);                                 \
        Is.y = fmaf(rv.y, hv.y, wv.y * xv.y);                                 \
        Is.z = fmaf(rv.z, hv.z, wv.z * xv.z);                                 \
        Is.w = fmaf(rv.w, hv.w, wv.w * xv.w);                                 \
        __stcs(qst + (size_t)(bb) * (NO_ * NI_ / 4), Is);                     \
        psum[(bb)] = (Is.x + Is.y) + (Is.z + Is.w);                           \
    }

    HSN_STEP(0) HSN_STEP(1) HSN_STEP(2) HSN_STEP(3)
    HSN_STEP(4) HSN_STEP(5) HSN_STEP(6) HSN_STEP(7)
#undef HSN_STEP

    // ---- Row-sum reduction (per batch), then scalar neuron update ----
    #pragma unroll
    for (int bb = 0; bb < NBT; ++bb) {
        #pragma unroll
        for (int off = 16; off > 0; off >>= 1)
            psum[bb] += __shfl_down_sync(0xFFFFFFFFu, psum[bb], off);
    }

    const int lane = t & 31;
    const int warp = t >> 5;
    if (lane == 0) {
        #pragma unroll
        for (int bb = 0; bb < NBT; ++bb) wsum[warp][bb] = psum[bb];
    }
    __syncthreads();

    if (t < NBT) {
        float v_in = 0.0f;
        #pragma unroll
        for (int k = 0; k < 8; ++k) v_in += wsum[k][t];

        const int b    = b0 + t;
        const int oidx = b * NO_ + j;

        const float Ir = fmaf(kRhoR, hIr[oidx], hz[oidx]);
        Ir_out[oidx] = Ir;
        // v = v_in - THR*Ir; z = (v - THR >= 0), THR = 1
        z_out[oidx]  = (v_in - Ir - 1.0f >= 0.0f) ? 1.0f : 0.0f;
    }
}

extern "C" void kernel_launch(void* const* d_in, const int* in_sizes, int n_in,
                              void* d_out, int out_size)
{
    // Input order per setup_inputs: x, w, rho, hz, hIsyn, hIr
    const float* x     = (const float*)d_in[0];
    const float* w     = (const float*)d_in[1];
    const float* rho   = (const float*)d_in[2];
    const float* hz    = (const float*)d_in[3];
    const float* hIsyn = (const float*)d_in[4];
    const float* hIr   = (const float*)d_in[5];

    // Output tuple (z, Isyn, Ir) flattened + concatenated
    float* out    = (float*)d_out;
    float* z_out  = out;
    float* Isyn_o = out + (size_t)B_ * NO_;
    float* Ir_out = out + (size_t)B_ * NO_ + (size_t)B_ * NO_ * NI_;

    dim3 grid(NO_, B_ / NBT);   // (1024, 8) = 8192 blocks
    dim3 block(256);
    hetsyn_cell_kernel<<<grid, block>>>(x, w, rho, hz, hIsyn, hIr,
                                        z_out, Isyn_o, Ir_out);
}

// round 6
// speedup vs baseline: 1.1004x; 1.0558x over previous
#include <cuda_runtime.h>
#include <cstdint>

// Problem constants (fixed by setup_inputs)
#define B_   64
#define NO_  1024
#define NI_  1024
#define NBT  8                     // batches per tile
#define NTILES (NO_ * (B_ / NBT))  // 8192 work units
#define NCTAS  608                 // 152 SMs x 4 resident CTAs

// RHO_R = exp(-DT/TAU_R) = exp(-0.05)
__device__ __constant__ float kRhoR = 0.95122942450071400910f;

// Persistent kernel: 608 CTAs grid-stride over 8192 (j, b-tile) units.
// Per tile: front-batch 8 streaming float4 loads of hIsyn (MLP=8, register
// resident), reuse register-cached rho/w row, FMA, streaming stores, then
// per-batch row reduction + neuron update. No wave quantization.
__global__ void __launch_bounds__(256, 4)
hetsyn_cell_kernel(const float* __restrict__ x,      // (B, NI)
                   const float* __restrict__ w,      // (NO, NI)
                   const float* __restrict__ rho,    // (NO, NI)
                   const float* __restrict__ hz,     // (B, NO)
                   const float* __restrict__ hIsyn,  // (B, NO, NI)
                   const float* __restrict__ hIr,    // (B, NO)
                   float* __restrict__ z_out,        // (B, NO)
                   float* __restrict__ Isyn_out,     // (B, NO, NI)
                   float* __restrict__ Ir_out)       // (B, NO)
{
    __shared__ float wsum[8][NBT];

    const int t    = threadIdx.x;       // 0..255
    const int lane = t & 31;
    const int warp = t >> 5;

    for (int tile = blockIdx.x; tile < NTILES; tile += NCTAS) {
        const int j  = tile & (NO_ - 1);
        const int b0 = (tile >> 10) * NBT;

        const size_t row0 = ((size_t)b0 * NO_ + j) * (size_t)NI_;

        // ---- Phase 1: front-batch all 8 streaming loads (MLP=8) ----
        float4 hv[NBT];
        {
            const float4* p = reinterpret_cast<const float4*>(hIsyn + row0) + t;
            #pragma unroll
            for (int bb = 0; bb < NBT; ++bb) {
                hv[bb] = __ldcs(p);
                p += (size_t)NO_ * NI_ / 4;
            }
        }

        // rho/w row: L2-resident after first wave (8 MB total)
        const size_t wrow = (size_t)j * NI_;
        const float4 rv = __ldg(reinterpret_cast<const float4*>(rho + wrow) + t);
        const float4 wv = __ldg(reinterpret_cast<const float4*>(w   + wrow) + t);

        // ---- Phase 2: compute, streaming store, partial sums ----
        float psum[NBT];
        {
            float4* q = reinterpret_cast<float4*>(Isyn_out + row0) + t;
            #pragma unroll
            for (int bb = 0; bb < NBT; ++bb) {
                const float4 xv = __ldg(reinterpret_cast<const float4*>(
                    x + (size_t)(b0 + bb) * NI_) + t);

                float4 Is;
                Is.x = fmaf(rv.x, hv[bb].x, wv.x * xv.x);
                Is.y = fmaf(rv.y, hv[bb].y, wv.y * xv.y);
                Is.z = fmaf(rv.z, hv[bb].z, wv.z * xv.z);
                Is.w = fmaf(rv.w, hv[bb].w, wv.w * xv.w);

                __stcs(q, Is);
                q += (size_t)NO_ * NI_ / 4;

                psum[bb] = (Is.x + Is.y) + (Is.z + Is.w);
            }
        }

        // ---- Row-sum reduction per batch ----
        #pragma unroll
        for (int bb = 0; bb < NBT; ++bb) {
            #pragma unroll
            for (int off = 16; off > 0; off >>= 1)
                psum[bb] += __shfl_down_sync(0xFFFFFFFFu, psum[bb], off);
        }

        if (lane == 0) {
            #pragma unroll
            for (int bb = 0; bb < NBT; ++bb) wsum[warp][bb] = psum[bb];
        }
        __syncthreads();

        if (t < NBT) {
            float v_in = 0.0f;
            #pragma unroll
            for (int k = 0; k < 8; ++k) v_in += wsum[k][t];

            const int oidx = (b0 + t) * NO_ + j;
            const float Ir = fmaf(kRhoR, hIr[oidx], hz[oidx]);
            Ir_out[oidx] = Ir;
            // v = v_in - THR*Ir; z = (v - THR >= 0), THR = 1
            z_out[oidx]  = (v_in - Ir - 1.0f >= 0.0f) ? 1.0f : 0.0f;
        }

        __syncthreads();   // protect wsum before next tile overwrites it
    }
}

extern "C" void kernel_launch(void* const* d_in, const int* in_sizes, int n_in,
                              void* d_out, int out_size)
{
    // Input order per setup_inputs: x, w, rho, hz, hIsyn, hIr
    const float* x     = (const float*)d_in[0];
    const float* w     = (const float*)d_in[1];
    const float* rho   = (const float*)d_in[2];
    const float* hz    = (const float*)d_in[3];
    const float* hIsyn = (const float*)d_in[4];
    const float* hIr   = (const float*)d_in[5];

    // Output tuple (z, Isyn, Ir) flattened + concatenated
    float* out    = (float*)d_out;
    float* z_out  = out;
    float* Isyn_o = out + (size_t)B_ * NO_;
    float* Ir_out = out + (size_t)B_ * NO_ + (size_t)B_ * NO_ * NI_;

    dim3 grid(NCTAS);   // persistent: 152 SMs x 4 CTAs
    dim3 block(256);
    hetsyn_cell_kernel<<<grid, block>>>(x, w, rho, hz, hIsyn, hIr,
                                        z_out, Isyn_o, Ir_out);
}